// round 10
// baseline (speedup 1.0000x reference)
#include <cuda_runtime.h>
#include <cuda_fp16.h>
#include <cstdint>

#define MM 16
#define KK 8192
#define NN 8192
#define KCH 8             // split-K chunks
#define KC 1024           // k per chunk (8 groups of 128)
#define RW 520            // smem x row stride in WORDS (== 8 mod 32 -> LDS.64 conflict-free)

// fp32 partials: [KCH][M][N]
__device__ float g_partial[KCH * MM * NN];

__device__ __forceinline__ void mma16816(float c[4],
                                         unsigned a0, unsigned a1, unsigned a2, unsigned a3,
                                         unsigned b0, unsigned b1) {
    asm volatile(
        "mma.sync.aligned.m16n8k16.row.col.f32.f16.f16.f32 "
        "{%0,%1,%2,%3}, {%4,%5,%6,%7}, {%8,%9}, {%0,%1,%2,%3};\n"
        : "+f"(c[0]), "+f"(c[1]), "+f"(c[2]), "+f"(c[3])
        : "r"(a0), "r"(a1), "r"(a2), "r"(a3), "r"(b0), "r"(b1));
}

// Nibbles t and t+4 of w -> exact fp16x2 (q-8, q'-8). Single shift+mask: no aliasing.
__device__ __forceinline__ unsigned dqx(unsigned w, unsigned sh4) {
    unsigned v = ((w >> sh4) & 0x000F000Fu) | 0x64006400u;   // (1024+q, 1024+q')
    __half2 hv = *reinterpret_cast<__half2*>(&v);
    __half2 r = __hsub2(hv, __float2half2_rn(1032.0f));      // exact
    return *reinterpret_cast<unsigned*>(&r);
}

__global__ __launch_bounds__(256, 3)
void q4_gemm_mma(const float* __restrict__ x,
                 const int* __restrict__ qw,
                 const float* __restrict__ scales) {
    __shared__ __align__(16) __half xs[MM * RW * 2];   // 16 rows * 520 words = 33280 B

    const int tid = threadIdx.x;
    const int kc = blockIdx.y;
    const int warp = tid >> 5;
    const int lane = tid & 31;
    const int g = lane >> 2;        // 0..7
    const int t = lane & 3;         // 0..3
    const unsigned sh4 = 4u * t;
    const int nbase = blockIdx.x * 128 + warp * 16;    // warp owns n16 (2 tiles)

    // ---- Stage x chunk [16][1024] -> word-interleaved fp16 layout ----
    // Per k16 step kt, 8 words: [b0w0,b1w0,b0w1,b1w1,b0w2,b1w2,b0w3,b1w3],
    // b0 = k 16kt..+7, b1 = +8..+15, bXwc = halves (k_c, k_{c+4}).
    for (int it = 0; it < 4; ++it) {
        int idx = it * 256 + tid;          // 1024 tasks: (m, kt)
        int m = idx >> 6;
        int kt = idx & 63;
        const float* xp = x + (size_t)m * KK + kc * KC + kt * 16;
        float4 lo0 = *reinterpret_cast<const float4*>(xp);
        float4 lo1 = *reinterpret_cast<const float4*>(xp + 4);
        float4 hi0 = *reinterpret_cast<const float4*>(xp + 8);
        float4 hi1 = *reinterpret_cast<const float4*>(xp + 12);
        __half2 w0 = __floats2half2_rn(lo0.x, lo1.x);   // (k0,k4)
        __half2 w1 = __floats2half2_rn(hi0.x, hi1.x);   // (k8,k12)
        __half2 w2 = __floats2half2_rn(lo0.y, lo1.y);   // (k1,k5)
        __half2 w3 = __floats2half2_rn(hi0.y, hi1.y);   // (k9,k13)
        __half2 w4 = __floats2half2_rn(lo0.z, lo1.z);   // (k2,k6)
        __half2 w5 = __floats2half2_rn(hi0.z, hi1.z);   // (k10,k14)
        __half2 w6 = __floats2half2_rn(lo0.w, lo1.w);   // (k3,k7)
        __half2 w7 = __floats2half2_rn(hi0.w, hi1.w);   // (k11,k15)
        uint4 p0, p1;
        p0.x = *reinterpret_cast<unsigned*>(&w0);
        p0.y = *reinterpret_cast<unsigned*>(&w1);
        p0.z = *reinterpret_cast<unsigned*>(&w2);
        p0.w = *reinterpret_cast<unsigned*>(&w3);
        p1.x = *reinterpret_cast<unsigned*>(&w4);
        p1.y = *reinterpret_cast<unsigned*>(&w5);
        p1.z = *reinterpret_cast<unsigned*>(&w6);
        p1.w = *reinterpret_cast<unsigned*>(&w7);
        __half* dst = &xs[(size_t)m * RW * 2 + kt * 16];
        *reinterpret_cast<uint4*>(dst)     = p0;
        *reinterpret_cast<uint4*>(dst + 8) = p1;
    }
    __syncthreads();

    // ---- Main loop: warp owns 2 interleaved n8-tiles (tile j col c -> n = nbase+2c+j) ----
    float cm[2][4];
#pragma unroll
    for (int j = 0; j < 2; ++j)
#pragma unroll
        for (int r = 0; r < 4; ++r) cm[j][r] = 0.f;

    const unsigned* xw = reinterpret_cast<const unsigned*>(xs);
    const int arow0 = g * RW;
    const int arow1 = (g + 8) * RW;

    for (int grp = 0; grp < 8; ++grp) {
        const int gidx = kc * 8 + grp;
        // Lane's 4 C-columns are contiguous: nbase + 4t .. +3
        const float4 sv = __ldg(reinterpret_cast<const float4*>(
            scales + (size_t)gidx * NN + nbase + 4 * t));

        float ct[2][4];
#pragma unroll
        for (int j = 0; j < 2; ++j)
#pragma unroll
            for (int r = 0; r < 4; ++r) ct[j][r] = 0.f;

#pragma unroll
        for (int kk8 = 0; kk8 < 8; ++kk8) {
            const int kt = grp * 8 + kk8;
            // Weights: lane's uint2 = rows 2kt/2kt+1, cols nbase+2g, +2g+1 (tiles 0,1)
            const int* rp = qw + (size_t)(kc * 128 + 2 * kt) * NN + nbase + 2 * g;
            uint2 q0 = __ldg(reinterpret_cast<const uint2*>(rp));        // row 2kt
            uint2 q1 = __ldg(reinterpret_cast<const uint2*>(rp + NN));   // row 2kt+1

            // A fragments: one LDS.64 per row (conflict-free)
            uint2 pa0 = *reinterpret_cast<const uint2*>(xw + arow0 + kt * 8 + 2 * t);
            uint2 pa1 = *reinterpret_cast<const uint2*>(xw + arow1 + kt * 8 + 2 * t);

            mma16816(ct[0], pa0.x, pa1.x, pa0.y, pa1.y, dqx(q0.x, sh4), dqx(q1.x, sh4));
            mma16816(ct[1], pa0.x, pa1.x, pa0.y, pa1.y, dqx(q0.y, sh4), dqx(q1.y, sh4));
        }

        // Scale map: col 4t+0 -> (j0,even), 4t+1 -> (j1,even), 4t+2 -> (j0,odd), 4t+3 -> (j1,odd)
        const float se[2] = {sv.x, sv.y};
        const float so[2] = {sv.z, sv.w};
#pragma unroll
        for (int j = 0; j < 2; ++j) {
            cm[j][0] += ct[j][0] * se[j];
            cm[j][1] += ct[j][1] * so[j];
            cm[j][2] += ct[j][2] * se[j];
            cm[j][3] += ct[j][3] * so[j];
        }
    }

    // ---- Store fp32 partials: lane covers cols nbase+4t..+3, rows {g, g+8} ----
    {
        float* p = g_partial + (size_t)kc * MM * NN;
        const int col = nbase + 4 * t;
        float4 v0 = make_float4(cm[0][0], cm[1][0], cm[0][1], cm[1][1]);   // row g
        float4 v1 = make_float4(cm[0][2], cm[1][2], cm[0][3], cm[1][3]);   // row g+8
        *reinterpret_cast<float4*>(p + (size_t)g * NN + col)       = v0;
        *reinterpret_cast<float4*>(p + (size_t)(g + 8) * NN + col) = v1;
    }
}

// One thread per 4 outputs: 32768 threads, 8 independent LDG.128 each.
__global__ __launch_bounds__(256)
void reduce_bias_kernel(const float* __restrict__ bias, float* __restrict__ out) {
    const int i4 = blockIdx.x * 256 + threadIdx.x;     // 0..32767
    const float4* pp = reinterpret_cast<const float4*>(g_partial);

    float4 s = __ldg(pp + i4);
#pragma unroll
    for (int c = 1; c < KCH; ++c) {
        float4 b = __ldg(pp + (size_t)c * (MM * NN / 4) + i4);
        s.x += b.x; s.y += b.y; s.z += b.z; s.w += b.w;
    }

    const int idx = i4 * 4;
    const int n = idx & (NN - 1);
    float4 bv = __ldg(reinterpret_cast<const float4*>(bias + n));
    // Reference fp16 epilogue: fp16(dot) + fp16(bias) in fp16.
    float4 o;
    o.x = __half2float(__hadd(__float2half_rn(s.x), __float2half_rn(bv.x)));
    o.y = __half2float(__hadd(__float2half_rn(s.y), __float2half_rn(bv.y)));
    o.z = __half2float(__hadd(__float2half_rn(s.z), __float2half_rn(bv.z)));
    o.w = __half2float(__hadd(__float2half_rn(s.w), __float2half_rn(bv.w)));
    *reinterpret_cast<float4*>(out + idx) = o;
}

extern "C" void kernel_launch(void* const* d_in, const int* in_sizes, int n_in,
                              void* d_out, int out_size) {
    // Identify inputs by element count (all distinct).
    const float* x    = nullptr;   // 131072
    const int*   qw   = nullptr;   // 8388608
    const float* sc   = nullptr;   // 524288
    const float* bias = nullptr;   // 8192
    for (int i = 0; i < n_in; ++i) {
        switch (in_sizes[i]) {
            case 131072:  x    = (const float*)d_in[i]; break;
            case 8388608: qw   = (const int*)d_in[i];   break;
            case 524288:  sc   = (const float*)d_in[i]; break;
            case 8192:    bias = (const float*)d_in[i]; break;
            default: break;
        }
    }
    float* out = (float*)d_out;

    dim3 grid(NN / 128, KCH);          // (64, 8), 256 threads (8 warps, n16 each)
    q4_gemm_mma<<<grid, 256>>>(x, qw, sc);

    reduce_bias_kernel<<<(MM * NN / 4) / 256, 256>>>(bias, out);
}